// round 2
// baseline (speedup 1.0000x reference)
#include <cuda_runtime.h>
#include <cuda_bf16.h>
#include <math.h>

// Problem constants (fixed by the reference):
//   N=200000 nodes, K_IN=8, K_OUT=4, E=800000 edges, D=64, H=128, O=1
#define MAX_N 200000
#define D_DIM 64
#define K_IN 8
#define K_OUT 4
#define H_DIM 128

// Scratch for pooled attention context [N, 64] (device global: allocation-rule safe)
__device__ float g_pooled[MAX_N * D_DIM];

// ---------------------------------------------------------------------------
// f32x2 packed-FMA helpers (sm_103a: scalar FFMA is half-rate; FFMA2 is full)
// ---------------------------------------------------------------------------
__device__ __forceinline__ unsigned long long pack2(float x, float y) {
    unsigned long long r;
    asm("mov.b64 %0, {%1, %2};" : "=l"(r) : "f"(x), "f"(y));
    return r;
}
__device__ __forceinline__ unsigned long long ffma2(unsigned long long a,
                                                    unsigned long long b,
                                                    unsigned long long c) {
    unsigned long long d;
    asm("fma.rn.f32x2 %0, %1, %2, %3;" : "=l"(d) : "l"(a), "l"(b), "l"(c));
    return d;
}
__device__ __forceinline__ float2 unpack2(unsigned long long v) {
    float2 r;
    asm("mov.b64 {%0, %1}, %2;" : "=f"(r.x), "=f"(r.y) : "l"(v));
    return r;
}

// ---------------------------------------------------------------------------
// Kernel 1: per-node self-attention over in-edges + pooled context
// One warp per node; 8 warps (256 threads) per block.
//
// Math note: pooled[d] = (1/denom) * sum_k w[k] * Ein[k][d],
//            w[k] = sum_{q: in_mask[q]} attn[q][k]
// so att_out never needs to be materialized.
// ---------------------------------------------------------------------------
__global__ void __launch_bounds__(256) attn_pool_kernel(
    const float* __restrict__ edges,
    const int* __restrict__ in_idx,
    const int* __restrict__ in_mask,
    int N)
{
    // padded rows: 68 floats per edge row -> conflict-free float4 column reads
    __shared__ float sE[8][K_IN * 68];

    const int lane = threadIdx.x & 31;
    const int w    = threadIdx.x >> 5;
    const int node = blockIdx.x * 8 + w;
    if (node >= N) return;

    float* sEw = &sE[w][0];

    // lanes 0..7 read this node's idx/mask
    int idx_l = 0, m_l = 0;
    if (lane < K_IN) {
        idx_l = in_idx[(size_t)node * K_IN + lane];
        m_l   = in_mask[(size_t)node * K_IN + lane];
    }

    // gather Ein rows: coalesced float2 per lane; keep register copy r[k]
    float2 r[K_IN];
#pragma unroll
    for (int k = 0; k < K_IN; ++k) {
        int ek = __shfl_sync(0xffffffffu, idx_l, k);
        float2 v = *(const float2*)(edges + (size_t)ek * D_DIM + lane * 2);
        r[k] = v;
        *(float2*)(sEw + k * 68 + lane * 2) = v;
    }
    __syncwarp();

    // scores: each lane computes pairs p0=lane, p1=lane+32
    //   p0: q0 = lane>>3, k = lane&7 ;  p1: q1 = q0+4, same k
    const int q0 = lane >> 3;
    const int kk = lane & 7;
    const float4* Eq0 = (const float4*)(sEw + q0 * 68);
    const float4* Eq1 = (const float4*)(sEw + (q0 + 4) * 68);
    const float4* Ekp = (const float4*)(sEw + kk * 68);

    float s0 = 0.f, s1 = 0.f;
#pragma unroll
    for (int d4 = 0; d4 < 16; ++d4) {
        float4 b  = Ekp[d4];
        float4 a0 = Eq0[d4];
        float4 a1 = Eq1[d4];
        s0 += a0.x * b.x + a0.y * b.y + a0.z * b.z + a0.w * b.w;
        s1 += a1.x * b.x + a1.y * b.y + a1.z * b.z + a1.w * b.w;
    }
    s0 *= 0.125f;   // 1/sqrt(64)
    s1 *= 0.125f;

    // key mask
    int mk = __shfl_sync(0xffffffffu, m_l, kk);
    if (!mk) { s0 = -1e9f; s1 = -1e9f; }

    // softmax over k within each 8-lane group (bits 0..2)
    float mx0 = s0, mx1 = s1;
#pragma unroll
    for (int o = 1; o < 8; o <<= 1) {
        mx0 = fmaxf(mx0, __shfl_xor_sync(0xffffffffu, mx0, o));
        mx1 = fmaxf(mx1, __shfl_xor_sync(0xffffffffu, mx1, o));
    }
    float e0 = __expf(s0 - mx0);
    float e1 = __expf(s1 - mx1);
    float z0 = e0, z1 = e1;
#pragma unroll
    for (int o = 1; o < 8; o <<= 1) {
        z0 += __shfl_xor_sync(0xffffffffu, z0, o);
        z1 += __shfl_xor_sync(0xffffffffu, z1, o);
    }
    float a0 = e0 / z0;   // attn[q0][kk]
    float a1 = e1 / z1;   // attn[q0+4][kk]

    // query masks for q0 and q0+4
    int mq0 = __shfl_sync(0xffffffffu, m_l, q0);
    int mq1 = __shfl_sync(0xffffffffu, m_l, q0 + 4);

    // w[k] = sum over valid queries of attn[q][k]; reduce over bits 3,4
    float v = (mq0 ? a0 : 0.f) + (mq1 ? a1 : 0.f);
    v += __shfl_xor_sync(0xffffffffu, v, 8);
    v += __shfl_xor_sync(0xffffffffu, v, 16);
    // every lane now holds w[lane & 7]

    // denom = max(count of valid queries, 1)
    int cnt = m_l;
#pragma unroll
    for (int o = 1; o < 32; o <<= 1)
        cnt += __shfl_xor_sync(0xffffffffu, cnt, o);
    float inv_denom = 1.f / fmaxf((float)cnt, 1.f);

    // pooled[2*lane .. 2*lane+1] = (sum_k w[k] * Ein[k][d]) / denom
    float px = 0.f, py = 0.f;
#pragma unroll
    for (int k = 0; k < K_IN; ++k) {
        float wk = __shfl_sync(0xffffffffu, v, k);
        px += wk * r[k].x;
        py += wk * r[k].y;
    }
    float2 p2 = make_float2(px * inv_denom, py * inv_denom);
    *(float2*)(g_pooled + (size_t)node * D_DIM + lane * 2) = p2;
}

// ---------------------------------------------------------------------------
// Kernel 2: fused 3-layer MLP over M = N*K_OUT rows.
//   x[128] = [edges[out_idx[row]] | pooled[row/4]]
//   y = Wout . relu(W1 . relu(W0 . x + b0) + b1) + bout, masked
// Tile: 64 rows per block, 256 threads, 4x8 micro-tile, FFMA2 accumulators.
// ---------------------------------------------------------------------------
#define MT 64
#define SX 132                      // padded X row stride (floats)
#define SMEM_FLOATS (MT * SX + H_DIM * H_DIM)

__global__ void __launch_bounds__(256, 2) mlp_kernel(
    const float* __restrict__ edges,
    const int* __restrict__ out_idx,
    const int* __restrict__ out_mask,
    const float* __restrict__ W0,
    const float* __restrict__ b0,
    const float* __restrict__ W1,
    const float* __restrict__ b1,
    const float* __restrict__ Wout,
    const float* __restrict__ bout,
    float* __restrict__ out,
    int M)
{
    extern __shared__ float smem[];
    float* Xs = smem;               // [MT][SX], cols 0..127 used
    float* Ws = smem + MT * SX;     // [128][128] transposed weights [k][h]

    const int t  = threadIdx.x;
    const int tx = t & 15;          // 16 column groups (8 h each)
    const int ty = t >> 4;          // 16 row groups (4 m each)
    const long base = (long)blockIdx.x * MT;

    // ---- load X tile: 16 threads per row, coalesced float4 ----
    {
        const int tg = t & 15;
        const int m0 = t >> 4;
#pragma unroll
        for (int rr = 0; rr < 4; ++rr) {
            int m = m0 + 16 * rr;
            long row = base + m;
            if (row < M) {
                int eidx = out_idx[row];
                long n = row >> 2;   // K_OUT = 4
                float4 e4 = *(const float4*)(edges + (size_t)eidx * D_DIM + tg * 4);
                float4 p4 = *(const float4*)(g_pooled + (size_t)n * D_DIM + tg * 4);
                *(float4*)(Xs + m * SX + tg * 4)          = e4;
                *(float4*)(Xs + m * SX + D_DIM + tg * 4)  = p4;
            } else {
                float4 z = make_float4(0.f, 0.f, 0.f, 0.f);
                *(float4*)(Xs + m * SX + tg * 4)          = z;
                *(float4*)(Xs + m * SX + D_DIM + tg * 4)  = z;
            }
        }
    }

    // ---- load W0 transposed into Ws[k][h] ----
    {
        const int h = t & 127;
        const int half = t >> 7;
#pragma unroll
        for (int it = 0; it < 16; ++it) {
            int k = half * 4 + it * 8;
            float4 wv = *(const float4*)(W0 + (size_t)h * H_DIM + k);
            Ws[(k + 0) * H_DIM + h] = wv.x;
            Ws[(k + 1) * H_DIM + h] = wv.y;
            Ws[(k + 2) * H_DIM + h] = wv.z;
            Ws[(k + 3) * H_DIM + h] = wv.w;
        }
    }
    __syncthreads();

    // ---- GEMM 1: H0[m][h] = sum_k X[m][k] * W0[h][k] ----
    unsigned long long acc[4][4];
#pragma unroll
    for (int i = 0; i < 4; ++i)
#pragma unroll
        for (int p = 0; p < 4; ++p) acc[i][p] = 0ULL;

    const float* xr0 = Xs + (4 * ty + 0) * SX;
    const float* xr1 = Xs + (4 * ty + 1) * SX;
    const float* xr2 = Xs + (4 * ty + 2) * SX;
    const float* xr3 = Xs + (4 * ty + 3) * SX;

#pragma unroll 8
    for (int k = 0; k < H_DIM; ++k) {
        ulonglong2 bu0 = *(const ulonglong2*)(Ws + k * H_DIM + 8 * tx);
        ulonglong2 bu1 = *(const ulonglong2*)(Ws + k * H_DIM + 8 * tx + 4);
        unsigned long long a0 = pack2(xr0[k], xr0[k]);
        unsigned long long a1 = pack2(xr1[k], xr1[k]);
        unsigned long long a2 = pack2(xr2[k], xr2[k]);
        unsigned long long a3 = pack2(xr3[k], xr3[k]);
        acc[0][0] = ffma2(a0, bu0.x, acc[0][0]);
        acc[0][1] = ffma2(a0, bu0.y, acc[0][1]);
        acc[0][2] = ffma2(a0, bu1.x, acc[0][2]);
        acc[0][3] = ffma2(a0, bu1.y, acc[0][3]);
        acc[1][0] = ffma2(a1, bu0.x, acc[1][0]);
        acc[1][1] = ffma2(a1, bu0.y, acc[1][1]);
        acc[1][2] = ffma2(a1, bu1.x, acc[1][2]);
        acc[1][3] = ffma2(a1, bu1.y, acc[1][3]);
        acc[2][0] = ffma2(a2, bu0.x, acc[2][0]);
        acc[2][1] = ffma2(a2, bu0.y, acc[2][1]);
        acc[2][2] = ffma2(a2, bu1.x, acc[2][2]);
        acc[2][3] = ffma2(a2, bu1.y, acc[2][3]);
        acc[3][0] = ffma2(a3, bu0.x, acc[3][0]);
        acc[3][1] = ffma2(a3, bu0.y, acc[3][1]);
        acc[3][2] = ffma2(a3, bu1.x, acc[3][2]);
        acc[3][3] = ffma2(a3, bu1.y, acc[3][3]);
    }

    // bias fragments for layer 0
    float4 bb0a = *(const float4*)(b0 + 8 * tx);
    float4 bb0b = *(const float4*)(b0 + 8 * tx + 4);
    float bj0[8] = {bb0a.x, bb0a.y, bb0a.z, bb0a.w, bb0b.x, bb0b.y, bb0b.z, bb0b.w};

    __syncthreads();  // everyone done reading Xs/Ws

    // ---- epilogue 1: relu(acc + b0) -> H0 into Xs[m][h] ----
#pragma unroll
    for (int i = 0; i < 4; ++i) {
#pragma unroll
        for (int p = 0; p < 4; ++p) {
            float2 vv = unpack2(acc[i][p]);
            vv.x = fmaxf(vv.x + bj0[2 * p], 0.f);
            vv.y = fmaxf(vv.y + bj0[2 * p + 1], 0.f);
            *(float2*)(Xs + (4 * ty + i) * SX + 8 * tx + 2 * p) = vv;
        }
    }

    // ---- load W1 transposed ----
    {
        const int h = t & 127;
        const int half = t >> 7;
#pragma unroll
        for (int it = 0; it < 16; ++it) {
            int k = half * 4 + it * 8;
            float4 wv = *(const float4*)(W1 + (size_t)h * H_DIM + k);
            Ws[(k + 0) * H_DIM + h] = wv.x;
            Ws[(k + 1) * H_DIM + h] = wv.y;
            Ws[(k + 2) * H_DIM + h] = wv.z;
            Ws[(k + 3) * H_DIM + h] = wv.w;
        }
    }
    __syncthreads();

    // ---- GEMM 2: H1[m][g] = sum_h H0[m][h] * W1[g][h] ----
#pragma unroll
    for (int i = 0; i < 4; ++i)
#pragma unroll
        for (int p = 0; p < 4; ++p) acc[i][p] = 0ULL;

#pragma unroll 8
    for (int k = 0; k < H_DIM; ++k) {
        ulonglong2 bu0 = *(const ulonglong2*)(Ws + k * H_DIM + 8 * tx);
        ulonglong2 bu1 = *(const ulonglong2*)(Ws + k * H_DIM + 8 * tx + 4);
        unsigned long long a0 = pack2(xr0[k], xr0[k]);
        unsigned long long a1 = pack2(xr1[k], xr1[k]);
        unsigned long long a2 = pack2(xr2[k], xr2[k]);
        unsigned long long a3 = pack2(xr3[k], xr3[k]);
        acc[0][0] = ffma2(a0, bu0.x, acc[0][0]);
        acc[0][1] = ffma2(a0, bu0.y, acc[0][1]);
        acc[0][2] = ffma2(a0, bu1.x, acc[0][2]);
        acc[0][3] = ffma2(a0, bu1.y, acc[0][3]);
        acc[1][0] = ffma2(a1, bu0.x, acc[1][0]);
        acc[1][1] = ffma2(a1, bu0.y, acc[1][1]);
        acc[1][2] = ffma2(a1, bu1.x, acc[1][2]);
        acc[1][3] = ffma2(a1, bu1.y, acc[1][3]);
        acc[2][0] = ffma2(a2, bu0.x, acc[2][0]);
        acc[2][1] = ffma2(a2, bu0.y, acc[2][1]);
        acc[2][2] = ffma2(a2, bu1.x, acc[2][2]);
        acc[2][3] = ffma2(a2, bu1.y, acc[2][3]);
        acc[3][0] = ffma2(a3, bu0.x, acc[3][0]);
        acc[3][1] = ffma2(a3, bu0.y, acc[3][1]);
        acc[3][2] = ffma2(a3, bu1.x, acc[3][2]);
        acc[3][3] = ffma2(a3, bu1.y, acc[3][3]);
    }

    // ---- epilogue 2: relu(+b1), dot with Wout, reduce over tx, store ----
    float4 bb1a = *(const float4*)(b1 + 8 * tx);
    float4 bb1b = *(const float4*)(b1 + 8 * tx + 4);
    float bj1[8] = {bb1a.x, bb1a.y, bb1a.z, bb1a.w, bb1b.x, bb1b.y, bb1b.z, bb1b.w};
    float4 woa = *(const float4*)(Wout + 8 * tx);
    float4 wob = *(const float4*)(Wout + 8 * tx + 4);
    float wo[8] = {woa.x, woa.y, woa.z, woa.w, wob.x, wob.y, wob.z, wob.w};
    float boutv = bout[0];

#pragma unroll
    for (int i = 0; i < 4; ++i) {
        float y = 0.f;
#pragma unroll
        for (int p = 0; p < 4; ++p) {
            float2 vv = unpack2(acc[i][p]);
            float hx = fmaxf(vv.x + bj1[2 * p], 0.f);
            float hy = fmaxf(vv.y + bj1[2 * p + 1], 0.f);
            y += wo[2 * p] * hx + wo[2 * p + 1] * hy;
        }
#pragma unroll
        for (int o = 1; o < 16; o <<= 1)
            y += __shfl_xor_sync(0xffffffffu, y, o);
        if (tx == 0) {
            long row = base + 4 * ty + i;
            if (row < M) {
                float om = (float)out_mask[row];
                out[row] = (y + boutv) * om;
            }
        }
    }
}

// ---------------------------------------------------------------------------
extern "C" void kernel_launch(void* const* d_in, const int* in_sizes, int n_in,
                              void* d_out, int out_size) {
    const float* edges   = (const float*)d_in[0];
    const int*   in_idx  = (const int*)d_in[1];
    const int*   in_mask = (const int*)d_in[2];
    const int*   out_idx = (const int*)d_in[3];
    const int*   out_mask= (const int*)d_in[4];
    const float* W0      = (const float*)d_in[5];
    const float* b0      = (const float*)d_in[6];
    const float* W1      = (const float*)d_in[7];
    const float* b1      = (const float*)d_in[8];
    const float* Wout    = (const float*)d_in[9];
    const float* bout    = (const float*)d_in[10];
    float* out = (float*)d_out;

    int N = in_sizes[1] / K_IN;     // 200000
    int M = N * K_OUT;              // 800000

    attn_pool_kernel<<<(N + 7) / 8, 256>>>(edges, in_idx, in_mask, N);

    size_t smem_bytes = (size_t)SMEM_FLOATS * sizeof(float);   // 99328
    cudaFuncSetAttribute(mlp_kernel,
                         cudaFuncAttributeMaxDynamicSharedMemorySize,
                         (int)smem_bytes);
    mlp_kernel<<<(M + MT - 1) / MT, 256, smem_bytes>>>(
        edges, out_idx, out_mask, W0, b0, W1, b1, Wout, bout, out, M);
}

// round 3
// speedup vs baseline: 1.5291x; 1.5291x over previous
#include <cuda_runtime.h>
#include <cuda_bf16.h>
#include <math.h>

// Problem constants (fixed by the reference):
//   N=200000 nodes, K_IN=8, K_OUT=4, E=800000 edges, D=64, H=128, O=1
#define MAX_N 200000
#define D_DIM 64
#define K_IN 8
#define K_OUT 4
#define H_DIM 128

// Scratch for pooled attention context [N, 64]
__device__ float g_pooled[MAX_N * D_DIM];

// ---------------------------------------------------------------------------
// f32x2 packed-FMA helpers
// ---------------------------------------------------------------------------
__device__ __forceinline__ unsigned long long pack2(float x, float y) {
    unsigned long long r;
    asm("mov.b64 %0, {%1, %2};" : "=l"(r) : "f"(x), "f"(y));
    return r;
}
__device__ __forceinline__ unsigned long long ffma2(unsigned long long a,
                                                    unsigned long long b,
                                                    unsigned long long c) {
    unsigned long long d;
    asm("fma.rn.f32x2 %0, %1, %2, %3;" : "=l"(d) : "l"(a), "l"(b), "l"(c));
    return d;
}
__device__ __forceinline__ float2 unpack2(unsigned long long v) {
    float2 r;
    asm("mov.b64 {%0, %1}, %2;" : "=f"(r.x), "=f"(r.y) : "l"(v));
    return r;
}

// ---------------------------------------------------------------------------
// Kernel 1: per-node self-attention over in-edges + pooled context
// (unchanged from R1 — ~190us, revisit later)
// ---------------------------------------------------------------------------
__global__ void __launch_bounds__(256) attn_pool_kernel(
    const float* __restrict__ edges,
    const int* __restrict__ in_idx,
    const int* __restrict__ in_mask,
    int N)
{
    __shared__ float sE[8][K_IN * 68];

    const int lane = threadIdx.x & 31;
    const int w    = threadIdx.x >> 5;
    const int node = blockIdx.x * 8 + w;
    if (node >= N) return;

    float* sEw = &sE[w][0];

    int idx_l = 0, m_l = 0;
    if (lane < K_IN) {
        idx_l = in_idx[(size_t)node * K_IN + lane];
        m_l   = in_mask[(size_t)node * K_IN + lane];
    }

    float2 r[K_IN];
#pragma unroll
    for (int k = 0; k < K_IN; ++k) {
        int ek = __shfl_sync(0xffffffffu, idx_l, k);
        float2 v = *(const float2*)(edges + (size_t)ek * D_DIM + lane * 2);
        r[k] = v;
        *(float2*)(sEw + k * 68 + lane * 2) = v;
    }
    __syncwarp();

    const int q0 = lane >> 3;
    const int kk = lane & 7;
    const float4* Eq0 = (const float4*)(sEw + q0 * 68);
    const float4* Eq1 = (const float4*)(sEw + (q0 + 4) * 68);
    const float4* Ekp = (const float4*)(sEw + kk * 68);

    float s0 = 0.f, s1 = 0.f;
#pragma unroll
    for (int d4 = 0; d4 < 16; ++d4) {
        float4 b  = Ekp[d4];
        float4 a0 = Eq0[d4];
        float4 a1 = Eq1[d4];
        s0 += a0.x * b.x + a0.y * b.y + a0.z * b.z + a0.w * b.w;
        s1 += a1.x * b.x + a1.y * b.y + a1.z * b.z + a1.w * b.w;
    }
    s0 *= 0.125f;
    s1 *= 0.125f;

    int mk = __shfl_sync(0xffffffffu, m_l, kk);
    if (!mk) { s0 = -1e9f; s1 = -1e9f; }

    float mx0 = s0, mx1 = s1;
#pragma unroll
    for (int o = 1; o < 8; o <<= 1) {
        mx0 = fmaxf(mx0, __shfl_xor_sync(0xffffffffu, mx0, o));
        mx1 = fmaxf(mx1, __shfl_xor_sync(0xffffffffu, mx1, o));
    }
    float e0 = __expf(s0 - mx0);
    float e1 = __expf(s1 - mx1);
    float z0 = e0, z1 = e1;
#pragma unroll
    for (int o = 1; o < 8; o <<= 1) {
        z0 += __shfl_xor_sync(0xffffffffu, z0, o);
        z1 += __shfl_xor_sync(0xffffffffu, z1, o);
    }
    float a0 = e0 / z0;
    float a1 = e1 / z1;

    int mq0 = __shfl_sync(0xffffffffu, m_l, q0);
    int mq1 = __shfl_sync(0xffffffffu, m_l, q0 + 4);

    float v = (mq0 ? a0 : 0.f) + (mq1 ? a1 : 0.f);
    v += __shfl_xor_sync(0xffffffffu, v, 8);
    v += __shfl_xor_sync(0xffffffffu, v, 16);

    int cnt = m_l;
#pragma unroll
    for (int o = 1; o < 32; o <<= 1)
        cnt += __shfl_xor_sync(0xffffffffu, cnt, o);
    float inv_denom = 1.f / fmaxf((float)cnt, 1.f);

    float px = 0.f, py = 0.f;
#pragma unroll
    for (int k = 0; k < K_IN; ++k) {
        float wk = __shfl_sync(0xffffffffu, v, k);
        px += wk * r[k].x;
        py += wk * r[k].y;
    }
    float2 p2 = make_float2(px * inv_denom, py * inv_denom);
    *(float2*)(g_pooled + (size_t)node * D_DIM + lane * 2) = p2;
}

// ---------------------------------------------------------------------------
// Kernel 2: fused 3-layer MLP, register-tiled 8x8 SGEMM with FFMA2.
// Block: 256 threads, tile 128 m x 128 h, 1 block/SM.
// Smem: Xt [128 k][132] (transposed activations) + Ws [128 k][132] (W^T).
// Warp layout: wm = (w&3)*32, wh = (w>>2)*64.
// Lane layout: mi = lane>>3 (m subgroup of 8 rows), hi = lane&7 (h subgroup).
// Thread tile: 8 m (as 4 f32x2 pairs) x 8 h.
// ---------------------------------------------------------------------------
#define KS 132
#define MLP_SMEM_BYTES (2 * 128 * KS * 4)

__device__ __forceinline__ void load_w_transposed(
    float* __restrict__ Ws, const float* __restrict__ W, int t)
{
    const int h    = t & 127;
    const int half = t >> 7;
    const float* wrow = W + (size_t)h * H_DIM + half * 64;
    float* dst = Ws + h;
#pragma unroll
    for (int it = 0; it < 16; ++it) {
        float4 wv = *(const float4*)(wrow + it * 4);
        int k = half * 64 + it * 4;
        dst[(k + 0) * KS] = wv.x;
        dst[(k + 1) * KS] = wv.y;
        dst[(k + 2) * KS] = wv.z;
        dst[(k + 3) * KS] = wv.w;
    }
}

__device__ __forceinline__ void gemm128(
    const float* __restrict__ Arow,   // Xt + wm + mi*8
    const float* __restrict__ Brow,   // Ws + wh + hi*8
    unsigned long long acc[4][8])
{
#pragma unroll 2
    for (int k = 0; k < H_DIM; ++k) {
        ulonglong2 au0 = *(const ulonglong2*)(Arow + (size_t)k * KS);
        ulonglong2 au1 = *(const ulonglong2*)(Arow + (size_t)k * KS + 4);
        float4 bv0 = *(const float4*)(Brow + (size_t)k * KS);
        float4 bv1 = *(const float4*)(Brow + (size_t)k * KS + 4);
        unsigned long long bs[8];
        bs[0] = pack2(bv0.x, bv0.x);
        bs[1] = pack2(bv0.y, bv0.y);
        bs[2] = pack2(bv0.z, bv0.z);
        bs[3] = pack2(bv0.w, bv0.w);
        bs[4] = pack2(bv1.x, bv1.x);
        bs[5] = pack2(bv1.y, bv1.y);
        bs[6] = pack2(bv1.z, bv1.z);
        bs[7] = pack2(bv1.w, bv1.w);
        unsigned long long ap[4] = {au0.x, au0.y, au1.x, au1.y};
#pragma unroll
        for (int p = 0; p < 4; ++p) {
#pragma unroll
            for (int j = 0; j < 8; ++j) {
                acc[p][j] = ffma2(ap[p], bs[j], acc[p][j]);
            }
        }
    }
}

__global__ void __launch_bounds__(256, 1) mlp_kernel(
    const float* __restrict__ edges,
    const int* __restrict__ out_idx,
    const int* __restrict__ out_mask,
    const float* __restrict__ W0,
    const float* __restrict__ b0,
    const float* __restrict__ W1,
    const float* __restrict__ b1,
    const float* __restrict__ Wout,
    const float* __restrict__ bout,
    float* __restrict__ out)
{
    extern __shared__ float smem[];
    float* Xt = smem;               // [128 k][KS]
    float* Ws = smem + 128 * KS;    // [128 k][KS]

    const int t    = threadIdx.x;
    const int lane = t & 31;
    const int w    = t >> 5;
    const int wm   = (w & 3) * 32;
    const int wh   = (w >> 2) * 64;
    const int mi   = lane >> 3;
    const int hi   = lane & 7;
    const long base = (long)blockIdx.x * 128;   // M = 800000 = 6250*128 exact

    // ---- load X tile transposed: Xt[k][m] ----
    {
        const int m    = t & 127;
        const int half = t >> 7;
        long row = base + m;
        int eidx = out_idx[row];
        const float* src = (half == 0)
            ? (edges + (size_t)eidx * D_DIM)
            : (g_pooled + (size_t)(row >> 2) * D_DIM);
        const int k0 = half * 64;
        float* dst = Xt + m;
#pragma unroll
        for (int it = 0; it < 16; ++it) {
            float4 v = *(const float4*)(src + it * 4);
            int k = k0 + it * 4;
            dst[(k + 0) * KS] = v.x;
            dst[(k + 1) * KS] = v.y;
            dst[(k + 2) * KS] = v.z;
            dst[(k + 3) * KS] = v.w;
        }
    }

    // ---- load W0 transposed ----
    load_w_transposed(Ws, W0, t);
    __syncthreads();

    const float* Arow = Xt + wm + mi * 8;
    const float* Brow = Ws + wh + hi * 8;

    // ---- GEMM 1 ----
    unsigned long long acc[4][8];
#pragma unroll
    for (int p = 0; p < 4; ++p)
#pragma unroll
        for (int j = 0; j < 8; ++j) acc[p][j] = 0ULL;

    gemm128(Arow, Brow, acc);

    // bias frag for layer 0 (this thread's 8 h-columns)
    float4 bb0a = *(const float4*)(b0 + wh + hi * 8);
    float4 bb0b = *(const float4*)(b0 + wh + hi * 8 + 4);
    float bj0[8] = {bb0a.x, bb0a.y, bb0a.z, bb0a.w, bb0b.x, bb0b.y, bb0b.z, bb0b.w};

    __syncthreads();   // all GEMM1 reads of Xt/Ws done

    // ---- epilogue 1: relu(acc + b0) -> Xt[h][m] (transposed for GEMM2) ----
#pragma unroll
    for (int j = 0; j < 8; ++j) {
        float* dst = Xt + (size_t)(wh + hi * 8 + j) * KS + wm + mi * 8;
#pragma unroll
        for (int p = 0; p < 4; ++p) {
            float2 vv = unpack2(acc[p][j]);
            vv.x = fmaxf(vv.x + bj0[j], 0.f);
            vv.y = fmaxf(vv.y + bj0[j], 0.f);
            *(float2*)(dst + 2 * p) = vv;
        }
    }

    // ---- load W1 transposed ----
    load_w_transposed(Ws, W1, t);
    __syncthreads();

    // ---- GEMM 2 ----
#pragma unroll
    for (int p = 0; p < 4; ++p)
#pragma unroll
        for (int j = 0; j < 8; ++j) acc[p][j] = 0ULL;

    gemm128(Arow, Brow, acc);

    // ---- final epilogue: relu(+b1), dot Wout, reduce, mask, store ----
    float4 bb1a = *(const float4*)(b1 + wh + hi * 8);
    float4 bb1b = *(const float4*)(b1 + wh + hi * 8 + 4);
    float bj1[8] = {bb1a.x, bb1a.y, bb1a.z, bb1a.w, bb1b.x, bb1b.y, bb1b.z, bb1b.w};
    float4 woa = *(const float4*)(Wout + wh + hi * 8);
    float4 wob = *(const float4*)(Wout + wh + hi * 8 + 4);
    float wo[8] = {woa.x, woa.y, woa.z, woa.w, wob.x, wob.y, wob.z, wob.w};

    float2 y[4];
#pragma unroll
    for (int p = 0; p < 4; ++p) {
        y[p] = make_float2(0.f, 0.f);
#pragma unroll
        for (int j = 0; j < 8; ++j) {
            float2 vv = unpack2(acc[p][j]);
            float hx = fmaxf(vv.x + bj1[j], 0.f);
            float hy = fmaxf(vv.y + bj1[j], 0.f);
            y[p].x += wo[j] * hx;
            y[p].y += wo[j] * hy;
        }
        // reduce across hi lanes (bits 0..2)
#pragma unroll
        for (int o = 1; o < 8; o <<= 1) {
            y[p].x += __shfl_xor_sync(0xffffffffu, y[p].x, o);
            y[p].y += __shfl_xor_sync(0xffffffffu, y[p].y, o);
        }
    }

    __syncthreads();   // Xt reads done everywhere; reuse as staging

    // stage partials: two warp-columns (wh 0 / 64) per m
    float* stage = Xt;   // stage[col*KS + m]
    if (hi == 0) {
        int col = w >> 2;
#pragma unroll
        for (int p = 0; p < 4; ++p) {
            *(float2*)(stage + (size_t)col * KS + wm + mi * 8 + 2 * p) = y[p];
        }
    }
    __syncthreads();

    if (t < 128) {
        long row = base + t;
        float yv = stage[t] + stage[KS + t] + bout[0];
        out[row] = yv * (float)out_mask[row];
    }
}

// ---------------------------------------------------------------------------
extern "C" void kernel_launch(void* const* d_in, const int* in_sizes, int n_in,
                              void* d_out, int out_size) {
    const float* edges   = (const float*)d_in[0];
    const int*   in_idx  = (const int*)d_in[1];
    const int*   in_mask = (const int*)d_in[2];
    const int*   out_idx = (const int*)d_in[3];
    const int*   out_mask= (const int*)d_in[4];
    const float* W0      = (const float*)d_in[5];
    const float* b0      = (const float*)d_in[6];
    const float* W1      = (const float*)d_in[7];
    const float* b1      = (const float*)d_in[8];
    const float* Wout    = (const float*)d_in[9];
    const float* bout    = (const float*)d_in[10];
    float* out = (float*)d_out;

    int N = in_sizes[1] / K_IN;     // 200000
    int M = N * K_OUT;              // 800000 = 6250 * 128

    attn_pool_kernel<<<(N + 7) / 8, 256>>>(edges, in_idx, in_mask, N);

    cudaFuncSetAttribute(mlp_kernel,
                         cudaFuncAttributeMaxDynamicSharedMemorySize,
                         MLP_SMEM_BYTES);
    mlp_kernel<<<M / 128, 256, MLP_SMEM_BYTES>>>(
        edges, out_idx, out_mask, W0, b0, W1, b1, Wout, bout, out);
}

// round 5
// speedup vs baseline: 1.5472x; 1.0119x over previous
#include <cuda_runtime.h>
#include <cuda_bf16.h>
#include <math.h>
#include <stdint.h>

// Problem constants: N=200000, K_IN=8, K_OUT=4, E=800000, D=64, H=128, O=1
#define MAX_N 200000
#define D_DIM 64
#define K_IN 8
#define K_OUT 4
#define H_DIM 128

__device__ float g_pooled[MAX_N * D_DIM];

// ---------------------------------------------------------------------------
// f32x2 packed-FMA helpers
// ---------------------------------------------------------------------------
__device__ __forceinline__ unsigned long long pack2s(float x) {
    unsigned long long r;
    asm("mov.b64 %0, {%1, %1};" : "=l"(r) : "f"(x));
    return r;
}
__device__ __forceinline__ unsigned long long ffma2(unsigned long long a,
                                                    unsigned long long b,
                                                    unsigned long long c) {
    unsigned long long d;
    asm("fma.rn.f32x2 %0, %1, %2, %3;" : "=l"(d) : "l"(a), "l"(b), "l"(c));
    return d;
}
__device__ __forceinline__ float2 unpack2(unsigned long long v) {
    float2 r;
    asm("mov.b64 {%0, %1}, %2;" : "=f"(r.x), "=f"(r.y) : "l"(v));
    return r;
}

// ---------------------------------------------------------------------------
// Kernel 1: per-node attention + pooled context (unchanged)
// ---------------------------------------------------------------------------
__global__ void __launch_bounds__(256) attn_pool_kernel(
    const float* __restrict__ edges,
    const int* __restrict__ in_idx,
    const int* __restrict__ in_mask,
    int N)
{
    __shared__ float sE[8][K_IN * 68];

    const int lane = threadIdx.x & 31;
    const int w    = threadIdx.x >> 5;
    const int node = blockIdx.x * 8 + w;
    if (node >= N) return;

    float* sEw = &sE[w][0];

    int idx_l = 0, m_l = 0;
    if (lane < K_IN) {
        idx_l = in_idx[(size_t)node * K_IN + lane];
        m_l   = in_mask[(size_t)node * K_IN + lane];
    }

    float2 r[K_IN];
#pragma unroll
    for (int k = 0; k < K_IN; ++k) {
        int ek = __shfl_sync(0xffffffffu, idx_l, k);
        float2 v = *(const float2*)(edges + (size_t)ek * D_DIM + lane * 2);
        r[k] = v;
        *(float2*)(sEw + k * 68 + lane * 2) = v;
    }
    __syncwarp();

    const int q0 = lane >> 3;
    const int kk = lane & 7;
    const float4* Eq0 = (const float4*)(sEw + q0 * 68);
    const float4* Eq1 = (const float4*)(sEw + (q0 + 4) * 68);
    const float4* Ekp = (const float4*)(sEw + kk * 68);

    float s0 = 0.f, s1 = 0.f;
#pragma unroll
    for (int d4 = 0; d4 < 16; ++d4) {
        float4 b  = Ekp[d4];
        float4 a0 = Eq0[d4];
        float4 a1 = Eq1[d4];
        s0 += a0.x * b.x + a0.y * b.y + a0.z * b.z + a0.w * b.w;
        s1 += a1.x * b.x + a1.y * b.y + a1.z * b.z + a1.w * b.w;
    }
    s0 *= 0.125f;
    s1 *= 0.125f;

    int mk = __shfl_sync(0xffffffffu, m_l, kk);
    if (!mk) { s0 = -1e9f; s1 = -1e9f; }

    float mx0 = s0, mx1 = s1;
#pragma unroll
    for (int o = 1; o < 8; o <<= 1) {
        mx0 = fmaxf(mx0, __shfl_xor_sync(0xffffffffu, mx0, o));
        mx1 = fmaxf(mx1, __shfl_xor_sync(0xffffffffu, mx1, o));
    }
    float e0 = __expf(s0 - mx0);
    float e1 = __expf(s1 - mx1);
    float z0 = e0, z1 = e1;
#pragma unroll
    for (int o = 1; o < 8; o <<= 1) {
        z0 += __shfl_xor_sync(0xffffffffu, z0, o);
        z1 += __shfl_xor_sync(0xffffffffu, z1, o);
    }
    float a0 = e0 / z0;
    float a1 = e1 / z1;

    int mq0 = __shfl_sync(0xffffffffu, m_l, q0);
    int mq1 = __shfl_sync(0xffffffffu, m_l, q0 + 4);

    float v = (mq0 ? a0 : 0.f) + (mq1 ? a1 : 0.f);
    v += __shfl_xor_sync(0xffffffffu, v, 8);
    v += __shfl_xor_sync(0xffffffffu, v, 16);

    int cnt = m_l;
#pragma unroll
    for (int o = 1; o < 32; o <<= 1)
        cnt += __shfl_xor_sync(0xffffffffu, cnt, o);
    float inv_denom = 1.f / fmaxf((float)cnt, 1.f);

    float px = 0.f, py = 0.f;
#pragma unroll
    for (int k = 0; k < K_IN; ++k) {
        float wk = __shfl_sync(0xffffffffu, v, k);
        px += wk * r[k].x;
        py += wk * r[k].y;
    }
    float2 p2 = make_float2(px * inv_denom, py * inv_denom);
    *(float2*)(g_pooled + (size_t)node * D_DIM + lane * 2) = p2;
}

// ---------------------------------------------------------------------------
// Kernel 2: fused 3-layer MLP, FFMA2 register tiling, 2 CTAs/SM.
// CTA: 256 threads, tile 64 m x 128 h.
// Smem: Xs [128 k][64 m] fp32, XOR-swizzled 16B chunks (key=(k>>3)&3), 32KB
//       Ws [128 k][128 h] fp32 (W^T, no swizzle needed),              64KB
// Warp layout: wm=(w&1)*32, wh=(w>>1)*32. Lane: lm=lane&7, lh=lane>>3.
// Thread tile: 4 m x 8 h (h as 4 f32x2 pairs). B read direct, A splatted.
// ---------------------------------------------------------------------------
#define XS_FLOATS (128 * 64)
#define WS_FLOATS (128 * 128)
#define MLP_SMEM_BYTES ((XS_FLOATS + WS_FLOATS) * 4)

// swizzled float index for X element (k, m)
__device__ __forceinline__ int xs_idx(int k, int m) {
    int chunk = (m >> 2) ^ ((k >> 3) & 3);
    return k * 64 + (chunk << 2) + (m & 3);
}

__device__ __forceinline__ void gemm_tile(
    const float* __restrict__ Xs,
    const float* __restrict__ Ws,
    int m0, int hbase,
    unsigned long long acc[4][4])
{
#pragma unroll 1
    for (int kb = 0; kb < 128; kb += 8) {
        const int key = (kb >> 3) & 3;
        const float4* Ar = (const float4*)(Xs + kb * 64) + ((m0 >> 2) ^ key);
        const float*  Br = Ws + kb * 128 + hbase;
#pragma unroll
        for (int kk = 0; kk < 8; ++kk) {
            float4 a = Ar[kk * 16];              // 16 float4 per 64-float row
            ulonglong2 b0 = *(const ulonglong2*)(Br + kk * 128);
            ulonglong2 b1 = *(const ulonglong2*)(Br + kk * 128 + 4);
            unsigned long long as0 = pack2s(a.x);
            unsigned long long as1 = pack2s(a.y);
            unsigned long long as2 = pack2s(a.z);
            unsigned long long as3 = pack2s(a.w);
            acc[0][0] = ffma2(as0, b0.x, acc[0][0]);
            acc[0][1] = ffma2(as0, b0.y, acc[0][1]);
            acc[0][2] = ffma2(as0, b1.x, acc[0][2]);
            acc[0][3] = ffma2(as0, b1.y, acc[0][3]);
            acc[1][0] = ffma2(as1, b0.x, acc[1][0]);
            acc[1][1] = ffma2(as1, b0.y, acc[1][1]);
            acc[1][2] = ffma2(as1, b1.x, acc[1][2]);
            acc[1][3] = ffma2(as1, b1.y, acc[1][3]);
            acc[2][0] = ffma2(as2, b0.x, acc[2][0]);
            acc[2][1] = ffma2(as2, b0.y, acc[2][1]);
            acc[2][2] = ffma2(as2, b1.x, acc[2][2]);
            acc[2][3] = ffma2(as2, b1.y, acc[2][3]);
            acc[3][0] = ffma2(as3, b0.x, acc[3][0]);
            acc[3][1] = ffma2(as3, b0.y, acc[3][1]);
            acc[3][2] = ffma2(as3, b1.x, acc[3][2]);
            acc[3][3] = ffma2(as3, b1.y, acc[3][3]);
        }
    }
}

// load W (H_DIM x H_DIM, row-major [h][k]) transposed into Ws[k][h]
__device__ __forceinline__ void load_w_T(
    float* __restrict__ Ws, const float* __restrict__ W, int t)
{
    const int h  = t & 127;
    const int k0 = (t >> 7) * 64;
    const float4* src = (const float4*)(W + (size_t)h * H_DIM + k0);
    float* dst = Ws + h;
#pragma unroll
    for (int it = 0; it < 16; ++it) {
        float4 wv = src[it];
        int k = k0 + it * 4;
        dst[(k + 0) * 128] = wv.x;
        dst[(k + 1) * 128] = wv.y;
        dst[(k + 2) * 128] = wv.z;
        dst[(k + 3) * 128] = wv.w;
    }
}

__global__ void __launch_bounds__(256, 2) mlp_kernel(
    const float* __restrict__ edges,
    const int* __restrict__ out_idx,
    const int* __restrict__ out_mask,
    const float* __restrict__ W0,
    const float* __restrict__ b0,
    const float* __restrict__ W1,
    const float* __restrict__ b1,
    const float* __restrict__ Wout,
    const float* __restrict__ bout,
    float* __restrict__ out)
{
    extern __shared__ float smem[];
    float* Xs = smem;                 // [128][64] swizzled
    float* Ws = smem + XS_FLOATS;     // [128][128]

    const int t    = threadIdx.x;
    const int lane = t & 31;
    const int w    = t >> 5;
    const int wm   = (w & 1) * 32;
    const int wh   = (w >> 1) * 32;
    const int lm   = lane & 7;
    const int lh   = lane >> 3;
    const int m0   = wm + lm * 4;
    const int hbase = wh + lh * 8;
    const long base = (long)blockIdx.x * 64;    // M = 800000 = 12500*64

    // ---- load X tile (swizzled): thread -> (m = t&63, k-quarter = t>>6) ----
    {
        const int m  = t & 63;
        const int kq = t >> 6;          // 0..3, 32 k each
        long row = base + m;
        const float* src;
        int k0 = kq * 32;
        if (kq < 2) {
            int eidx = out_idx[row];
            src = edges + (size_t)eidx * D_DIM + k0;
        } else {
            src = g_pooled + (size_t)(row >> 2) * D_DIM + (k0 - 64);
        }
#pragma unroll
        for (int i = 0; i < 8; ++i) {
            float4 v = *(const float4*)(src + i * 4);
            int k = k0 + i * 4;
            Xs[xs_idx(k + 0, m)] = v.x;
            Xs[xs_idx(k + 1, m)] = v.y;
            Xs[xs_idx(k + 2, m)] = v.z;
            Xs[xs_idx(k + 3, m)] = v.w;
        }
    }

    load_w_T(Ws, W0, t);
    __syncthreads();

    // ---- GEMM 1 ----
    unsigned long long acc[4][4];
#pragma unroll
    for (int i = 0; i < 4; ++i)
#pragma unroll
        for (int p = 0; p < 4; ++p) acc[i][p] = 0ULL;

    gemm_tile(Xs, Ws, m0, hbase, acc);

    float4 b0a = *(const float4*)(b0 + hbase);
    float4 b0b = *(const float4*)(b0 + hbase + 4);
    float bj0[8] = {b0a.x, b0a.y, b0a.z, b0a.w, b0b.x, b0b.y, b0b.z, b0b.w};

    __syncthreads();   // all reads of Xs/Ws done

    // ---- epilogue 1: relu(+b0) -> Xs[h][m] (transposed, swizzled) ----
#pragma unroll
    for (int p = 0; p < 4; ++p) {
        float2 v0 = unpack2(acc[0][p]);
        float2 v1 = unpack2(acc[1][p]);
        float2 v2 = unpack2(acc[2][p]);
        float2 v3 = unpack2(acc[3][p]);
        int hx = hbase + 2 * p;
        float4 fx = make_float4(fmaxf(v0.x + bj0[2*p], 0.f),
                                fmaxf(v1.x + bj0[2*p], 0.f),
                                fmaxf(v2.x + bj0[2*p], 0.f),
                                fmaxf(v3.x + bj0[2*p], 0.f));
        float4 fy = make_float4(fmaxf(v0.y + bj0[2*p+1], 0.f),
                                fmaxf(v1.y + bj0[2*p+1], 0.f),
                                fmaxf(v2.y + bj0[2*p+1], 0.f),
                                fmaxf(v3.y + bj0[2*p+1], 0.f));
        *(float4*)(Xs + xs_idx(hx,     m0)) = fx;
        *(float4*)(Xs + xs_idx(hx + 1, m0)) = fy;
    }

    load_w_T(Ws, W1, t);
    __syncthreads();

    // ---- GEMM 2 ----
#pragma unroll
    for (int i = 0; i < 4; ++i)
#pragma unroll
        for (int p = 0; p < 4; ++p) acc[i][p] = 0ULL;

    gemm_tile(Xs, Ws, m0, hbase, acc);

    // ---- final epilogue: relu(+b1), dot with Wout over this thread's 8 h ----
    float4 b1a = *(const float4*)(b1 + hbase);
    float4 b1b = *(const float4*)(b1 + hbase + 4);
    float bj1[8] = {b1a.x, b1a.y, b1a.z, b1a.w, b1b.x, b1b.y, b1b.z, b1b.w};
    float4 woa = *(const float4*)(Wout + hbase);
    float4 wob = *(const float4*)(Wout + hbase + 4);
    float wo[8] = {woa.x, woa.y, woa.z, woa.w, wob.x, wob.y, wob.z, wob.w};

    float y[4] = {0.f, 0.f, 0.f, 0.f};
#pragma unroll
    for (int p = 0; p < 4; ++p) {
#pragma unroll
        for (int i = 0; i < 4; ++i) {
            float2 vv = unpack2(acc[i][p]);
            y[i] += wo[2*p]   * fmaxf(vv.x + bj1[2*p],   0.f);
            y[i] += wo[2*p+1] * fmaxf(vv.y + bj1[2*p+1], 0.f);
        }
    }

    __syncthreads();   // GEMM2 reads done; reuse Xs as staging

    // stage partials: 16 partial rows (4 wh-groups x 4 lh) x 64 m, stride 68
    {
        int part = (w >> 1) * 4 + lh;
        *(float4*)(Xs + part * 68 + m0) = make_float4(y[0], y[1], y[2], y[3]);
    }
    __syncthreads();

    if (t < 64) {
        long row = base + t;
        float s = bout[0];
#pragma unroll
        for (int p = 0; p < 16; ++p) s += Xs[p * 68 + t];
        out[row] = s * (float)out_mask[row];
    }
}

// ---------------------------------------------------------------------------
extern "C" void kernel_launch(void* const* d_in, const int* in_sizes, int n_in,
                              void* d_out, int out_size) {
    const float* edges   = (const float*)d_in[0];
    const int*   in_idx  = (const int*)d_in[1];
    const int*   in_mask = (const int*)d_in[2];
    const int*   out_idx = (const int*)d_in[3];
    const int*   out_mask= (const int*)d_in[4];
    const float* W0      = (const float*)d_in[5];
    const float* b0      = (const float*)d_in[6];
    const float* W1      = (const float*)d_in[7];
    const float* b1      = (const float*)d_in[8];
    const float* Wout    = (const float*)d_in[9];
    const float* bout    = (const float*)d_in[10];
    float* out = (float*)d_out;

    int N = in_sizes[1] / K_IN;     // 200000
    int M = N * K_OUT;              // 800000 = 12500 * 64

    attn_pool_kernel<<<(N + 7) / 8, 256>>>(edges, in_idx, in_mask, N);

    cudaFuncSetAttribute(mlp_kernel,
                         cudaFuncAttributeMaxDynamicSharedMemorySize,
                         MLP_SMEM_BYTES);
    mlp_kernel<<<M / 64, 256, MLP_SMEM_BYTES>>>(
        edges, out_idx, out_mask, W0, b0, W1, b1, Wout, bout, out);
}

// round 6
// speedup vs baseline: 1.9099x; 1.2344x over previous
#include <cuda_runtime.h>
#include <cuda_bf16.h>
#include <math.h>
#include <stdint.h>

// Problem constants: N=200000, K_IN=8, K_OUT=4, E=800000, D=64, H=128, O=1
#define MAX_N 200000
#define D_DIM 64
#define K_IN 8
#define K_OUT 4
#define H_DIM 128

__device__ float g_pooled[MAX_N * D_DIM];

// ---------------------------------------------------------------------------
// helpers
// ---------------------------------------------------------------------------
__device__ __forceinline__ uint32_t smem_u32(const void* p) {
    uint32_t a;
    asm("{ .reg .u64 t; cvta.to.shared.u64 t, %1; cvt.u32.u64 %0, t; }"
        : "=r"(a) : "l"(p));
    return a;
}

// pack two floats to bf16x2: lo -> bits[15:0], hi -> bits[31:16]
__device__ __forceinline__ uint32_t bf16x2_rn(float lo, float hi) {
    uint32_t r;
    asm("cvt.rn.bf16x2.f32 %0, %1, %2;" : "=r"(r) : "f"(hi), "f"(lo));
    return r;
}

// split 8 fp32 into hi-bf16 16B chunk + lo-bf16 16B chunk
__device__ __forceinline__ void split8(const float* f, uint4& hv, uint4& lv) {
    float hf[8], lf[8];
#pragma unroll
    for (int i = 0; i < 8; ++i) {
        __nv_bfloat16 hb = __float2bfloat16(f[i]);
        hf[i] = __bfloat162float(hb);
        lf[i] = f[i] - hf[i];
    }
    hv.x = bf16x2_rn(hf[0], hf[1]); hv.y = bf16x2_rn(hf[2], hf[3]);
    hv.z = bf16x2_rn(hf[4], hf[5]); hv.w = bf16x2_rn(hf[6], hf[7]);
    lv.x = bf16x2_rn(lf[0], lf[1]); lv.y = bf16x2_rn(lf[2], lf[3]);
    lv.z = bf16x2_rn(lf[4], lf[5]); lv.w = bf16x2_rn(lf[6], lf[7]);
}

#define LDMX4(r0, r1, r2, r3, addr) \
    asm volatile("ldmatrix.sync.aligned.m8n8.x4.shared.b16 {%0,%1,%2,%3}, [%4];" \
        : "=r"(r0), "=r"(r1), "=r"(r2), "=r"(r3) : "r"(addr))

#define MMA16816(c, a, b) \
    asm volatile("mma.sync.aligned.m16n8k16.row.col.f32.bf16.bf16.f32 " \
        "{%0,%1,%2,%3}, {%4,%5,%6,%7}, {%8,%9}, {%0,%1,%2,%3};" \
        : "+f"((c)[0]), "+f"((c)[1]), "+f"((c)[2]), "+f"((c)[3]) \
        : "r"((a)[0]), "r"((a)[1]), "r"((a)[2]), "r"((a)[3]), \
          "r"((b)[0]), "r"((b)[1]))

// ---------------------------------------------------------------------------
// Kernel 1: per-node attention + pooled context (unchanged)
// ---------------------------------------------------------------------------
__global__ void __launch_bounds__(256) attn_pool_kernel(
    const float* __restrict__ edges,
    const int* __restrict__ in_idx,
    const int* __restrict__ in_mask,
    int N)
{
    __shared__ float sE[8][K_IN * 68];

    const int lane = threadIdx.x & 31;
    const int w    = threadIdx.x >> 5;
    const int node = blockIdx.x * 8 + w;
    if (node >= N) return;

    float* sEw = &sE[w][0];

    int idx_l = 0, m_l = 0;
    if (lane < K_IN) {
        idx_l = in_idx[(size_t)node * K_IN + lane];
        m_l   = in_mask[(size_t)node * K_IN + lane];
    }

    float2 r[K_IN];
#pragma unroll
    for (int k = 0; k < K_IN; ++k) {
        int ek = __shfl_sync(0xffffffffu, idx_l, k);
        float2 v = *(const float2*)(edges + (size_t)ek * D_DIM + lane * 2);
        r[k] = v;
        *(float2*)(sEw + k * 68 + lane * 2) = v;
    }
    __syncwarp();

    const int q0 = lane >> 3;
    const int kk = lane & 7;
    const float4* Eq0 = (const float4*)(sEw + q0 * 68);
    const float4* Eq1 = (const float4*)(sEw + (q0 + 4) * 68);
    const float4* Ekp = (const float4*)(sEw + kk * 68);

    float s0 = 0.f, s1 = 0.f;
#pragma unroll
    for (int d4 = 0; d4 < 16; ++d4) {
        float4 b  = Ekp[d4];
        float4 a0 = Eq0[d4];
        float4 a1 = Eq1[d4];
        s0 += a0.x * b.x + a0.y * b.y + a0.z * b.z + a0.w * b.w;
        s1 += a1.x * b.x + a1.y * b.y + a1.z * b.z + a1.w * b.w;
    }
    s0 *= 0.125f;
    s1 *= 0.125f;

    int mk = __shfl_sync(0xffffffffu, m_l, kk);
    if (!mk) { s0 = -1e9f; s1 = -1e9f; }

    float mx0 = s0, mx1 = s1;
#pragma unroll
    for (int o = 1; o < 8; o <<= 1) {
        mx0 = fmaxf(mx0, __shfl_xor_sync(0xffffffffu, mx0, o));
        mx1 = fmaxf(mx1, __shfl_xor_sync(0xffffffffu, mx1, o));
    }
    float e0 = __expf(s0 - mx0);
    float e1 = __expf(s1 - mx1);
    float z0 = e0, z1 = e1;
#pragma unroll
    for (int o = 1; o < 8; o <<= 1) {
        z0 += __shfl_xor_sync(0xffffffffu, z0, o);
        z1 += __shfl_xor_sync(0xffffffffu, z1, o);
    }
    float a0 = e0 / z0;
    float a1 = e1 / z1;

    int mq0 = __shfl_sync(0xffffffffu, m_l, q0);
    int mq1 = __shfl_sync(0xffffffffu, m_l, q0 + 4);

    float v = (mq0 ? a0 : 0.f) + (mq1 ? a1 : 0.f);
    v += __shfl_xor_sync(0xffffffffu, v, 8);
    v += __shfl_xor_sync(0xffffffffu, v, 16);

    int cnt = m_l;
#pragma unroll
    for (int o = 1; o < 32; o <<= 1)
        cnt += __shfl_xor_sync(0xffffffffu, cnt, o);
    float inv_denom = 1.f / fmaxf((float)cnt, 1.f);

    float px = 0.f, py = 0.f;
#pragma unroll
    for (int k = 0; k < K_IN; ++k) {
        float wk = __shfl_sync(0xffffffffu, v, k);
        px += wk * r[k].x;
        py += wk * r[k].y;
    }
    float2 p2 = make_float2(px * inv_denom, py * inv_denom);
    *(float2*)(g_pooled + (size_t)node * D_DIM + lane * 2) = p2;
}

// ---------------------------------------------------------------------------
// Kernel 2: fused 3-layer MLP with HMMA (mma.sync m16n8k16 bf16, hi/lo split).
// CTA: 256 threads (8 warps), 64 rows. 2 CTAs/SM.
// SMEM byte layout (per CTA):
//   XHI@0      [64 m][128 k] bf16  (16 KB)    rows 256B, 16B-chunk XOR swizzle
//   XLO@16384  (16 KB)
//   WHI@32768  [128 h][128 k] bf16 (32 KB)
//   WLO@65536  (32 KB)
//   STG@98304  4 x 64 fp32 partials (1 KB)
// Warp grid: m0 = (w&1)*32, n0 = (w>>1)*32; warp tile 32m x 32n.
// ---------------------------------------------------------------------------
#define XHI_B 0u
#define XLO_B 16384u
#define WHI_B 32768u
#define WLO_B 65536u
#define STG_B 98304u
#define MLP_SMEM_BYTES 99328

// byte offset inside a buffer for (row, 16B-chunk)
__device__ __forceinline__ uint32_t swz(int row, int chunk) {
    return (uint32_t)row * 256u + (uint32_t)((chunk ^ (row & 7)) << 4);
}

// one accumulate pass: acc += Xbuf * Wbuf^T over k=128
__device__ __forceinline__ void gemm_pass(
    uint32_t xbase, uint32_t wbase,
    uint32_t aOff0, uint32_t aOff1, uint32_t aKey, uint32_t cbA,
    uint32_t bOff0, uint32_t bOff1, uint32_t bKey, uint32_t cbB,
    float acc[2][4][4])
{
#pragma unroll
    for (int kc = 0; kc < 8; ++kc) {
        uint32_t ca = (uint32_t)((((2 * kc + cbA)) ^ aKey) << 4);
        uint32_t cb = (uint32_t)((((2 * kc + cbB)) ^ bKey) << 4);
        uint32_t a0r[4], a1r[4], bq0[4], bq1[4];
        LDMX4(a0r[0], a0r[1], a0r[2], a0r[3], xbase + aOff0 + ca);
        LDMX4(a1r[0], a1r[1], a1r[2], a1r[3], xbase + aOff1 + ca);
        LDMX4(bq0[0], bq0[1], bq0[2], bq0[3], wbase + bOff0 + cb);
        LDMX4(bq1[0], bq1[1], bq1[2], bq1[3], wbase + bOff1 + cb);
        MMA16816(acc[0][0], a0r, bq0 + 0);
        MMA16816(acc[0][1], a0r, bq0 + 2);
        MMA16816(acc[0][2], a0r, bq1 + 0);
        MMA16816(acc[0][3], a0r, bq1 + 2);
        MMA16816(acc[1][0], a1r, bq0 + 0);
        MMA16816(acc[1][1], a1r, bq0 + 2);
        MMA16816(acc[1][2], a1r, bq1 + 0);
        MMA16816(acc[1][3], a1r, bq1 + 2);
    }
}

// load weight matrix W [128][128] fp32 -> hi/lo bf16 buffers (swizzled)
__device__ __forceinline__ void load_w_split(
    char* smem, uint32_t hi_off, uint32_t lo_off,
    const float* __restrict__ W, int t)
{
    const int h    = t & 127;
    const int half = t >> 7;
    const int key  = h & 7;
    const float4* src = (const float4*)(W + (size_t)h * H_DIM + half * 64);
#pragma unroll
    for (int c = 0; c < 8; ++c) {
        float4 f0 = src[2 * c], f1 = src[2 * c + 1];
        float f[8] = {f0.x, f0.y, f0.z, f0.w, f1.x, f1.y, f1.z, f1.w};
        uint4 hv, lv;
        split8(f, hv, lv);
        int chunk = half * 8 + c;
        uint32_t off = (uint32_t)h * 256u + (uint32_t)((chunk ^ key) << 4);
        *(uint4*)(smem + hi_off + off) = hv;
        *(uint4*)(smem + lo_off + off) = lv;
    }
}

__global__ void __launch_bounds__(256, 2) mlp_kernel(
    const float* __restrict__ edges,
    const int* __restrict__ out_idx,
    const int* __restrict__ out_mask,
    const float* __restrict__ W0,
    const float* __restrict__ b0,
    const float* __restrict__ W1,
    const float* __restrict__ b1,
    const float* __restrict__ Wout,
    const float* __restrict__ bout,
    float* __restrict__ out)
{
    extern __shared__ char smem[];
    const uint32_t sb = smem_u32(smem);

    const int t    = threadIdx.x;
    const int lane = t & 31;
    const int w    = t >> 5;
    const int gid  = lane >> 2;     // 0..7
    const int tig  = lane & 3;      // 0..3
    const int m0   = (w & 1) * 32;
    const int n0   = (w >> 1) * 32;
    const long base = (long)blockIdx.x * 64;    // M = 800000 = 12500*64

    // ---- load X = [edges | pooled] -> hi/lo bf16 swizzled ----
    {
        const int row = t & 63;
        const int kq  = t >> 6;     // 0..3 (32 k each)
        long grow = base + row;
        const float* src;
        if (kq < 2) {
            int eidx = out_idx[grow];
            src = edges + (size_t)eidx * D_DIM + kq * 32;
        } else {
            src = g_pooled + (size_t)(grow >> 2) * D_DIM + (kq - 2) * 32;
        }
        const float4* s4 = (const float4*)src;
        const int cbase = kq * 4;
#pragma unroll
        for (int c = 0; c < 4; ++c) {
            float4 f0 = s4[2 * c], f1 = s4[2 * c + 1];
            float f[8] = {f0.x, f0.y, f0.z, f0.w, f1.x, f1.y, f1.z, f1.w};
            uint4 hv, lv;
            split8(f, hv, lv);
            uint32_t off = swz(row, cbase + c);
            *(uint4*)(smem + XHI_B + off) = hv;
            *(uint4*)(smem + XLO_B + off) = lv;
        }
    }
    load_w_split(smem, WHI_B, WLO_B, W0, t);
    __syncthreads();

    // ---- per-lane ldmatrix geometry ----
    const int sub = lane >> 3;      // 0..3 (matrix slot)
    const int r8  = lane & 7;
    const int aRow = m0 + (sub & 1) * 8 + r8;       // i=0 tile; i=1 adds 16
    const uint32_t aOff0 = (uint32_t)aRow * 256u;
    const uint32_t aOff1 = (uint32_t)(aRow + 16) * 256u;
    const uint32_t aKey  = (uint32_t)(aRow & 7);
    const uint32_t cbA   = (uint32_t)(sub >> 1);
    const int bRow = n0 + (sub >> 1) * 8 + r8;      // j=0 tile; j=1 adds 16
    const uint32_t bOff0 = (uint32_t)bRow * 256u;
    const uint32_t bOff1 = (uint32_t)(bRow + 16) * 256u;
    const uint32_t bKey  = (uint32_t)(bRow & 7);
    const uint32_t cbB   = (uint32_t)(sub & 1);

    const uint32_t XH = sb + XHI_B, XL = sb + XLO_B;
    const uint32_t WH = sb + WHI_B, WL = sb + WLO_B;

    // ---- GEMM layer 1: acc = Xhi*Whi + Xhi*Wlo + Xlo*Whi ----
    float acc[2][4][4];
#pragma unroll
    for (int i = 0; i < 2; ++i)
#pragma unroll
        for (int j = 0; j < 4; ++j)
#pragma unroll
            for (int p = 0; p < 4; ++p) acc[i][j][p] = 0.f;

    gemm_pass(XH, WH, aOff0, aOff1, aKey, cbA, bOff0, bOff1, bKey, cbB, acc);
    gemm_pass(XH, WL, aOff0, aOff1, aKey, cbA, bOff0, bOff1, bKey, cbB, acc);
    gemm_pass(XL, WH, aOff0, aOff1, aKey, cbA, bOff0, bOff1, bKey, cbB, acc);

    __syncthreads();   // all reads of X/W done

    // ---- epilogue 1: H = relu(acc + b0) -> X buffers (bf16 hi/lo) ----
#pragma unroll
    for (int j = 0; j < 4; ++j) {
        int h0 = n0 + 8 * j + 2 * tig;
        float2 bb = *(const float2*)(b0 + h0);
        int chunk = (n0 + 8 * j) >> 3;
        uint32_t cof = (uint32_t)(tig * 4);
#pragma unroll
        for (int i = 0; i < 2; ++i) {
            // rows gid and gid+8
#pragma unroll
            for (int rs = 0; rs < 2; ++rs) {
                int row = m0 + 16 * i + 8 * rs + gid;
                float v0 = fmaxf(acc[i][j][2 * rs]     + bb.x, 0.f);
                float v1 = fmaxf(acc[i][j][2 * rs + 1] + bb.y, 0.f);
                __nv_bfloat16 h0b = __float2bfloat16(v0);
                __nv_bfloat16 h1b = __float2bfloat16(v1);
                float l0 = v0 - __bfloat162float(h0b);
                float l1 = v1 - __bfloat162float(h1b);
                uint32_t hw = bf16x2_rn(__bfloat162float(h0b), __bfloat162float(h1b));
                uint32_t lw = bf16x2_rn(l0, l1);
                uint32_t off = (uint32_t)row * 256u
                             + (uint32_t)((chunk ^ (row & 7)) << 4) + cof;
                *(uint32_t*)(smem + XHI_B + off) = hw;
                *(uint32_t*)(smem + XLO_B + off) = lw;
            }
        }
    }
    load_w_split(smem, WHI_B, WLO_B, W1, t);
    __syncthreads();

    // ---- GEMM layer 2 ----
#pragma unroll
    for (int i = 0; i < 2; ++i)
#pragma unroll
        for (int j = 0; j < 4; ++j)
#pragma unroll
            for (int p = 0; p < 4; ++p) acc[i][j][p] = 0.f;

    gemm_pass(XH, WH, aOff0, aOff1, aKey, cbA, bOff0, bOff1, bKey, cbB, acc);
    gemm_pass(XH, WL, aOff0, aOff1, aKey, cbA, bOff0, bOff1, bKey, cbB, acc);
    gemm_pass(XL, WH, aOff0, aOff1, aKey, cbA, bOff0, bOff1, bKey, cbB, acc);

    // ---- final epilogue: relu(+b1), dot Wout, reduce ----
    float y[2][2] = {{0.f, 0.f}, {0.f, 0.f}};   // [i][rowsub]
#pragma unroll
    for (int j = 0; j < 4; ++j) {
        int h0 = n0 + 8 * j + 2 * tig;
        float2 bb = *(const float2*)(b1 + h0);
        float2 ww = *(const float2*)(Wout + h0);
#pragma unroll
        for (int i = 0; i < 2; ++i) {
#pragma unroll
            for (int rs = 0; rs < 2; ++rs) {
                float v0 = fmaxf(acc[i][j][2 * rs]     + bb.x, 0.f);
                float v1 = fmaxf(acc[i][j][2 * rs + 1] + bb.y, 0.f);
                y[i][rs] += ww.x * v0 + ww.y * v1;
            }
        }
    }
    // reduce over tig lanes (bits 0,1)
#pragma unroll
    for (int i = 0; i < 2; ++i)
#pragma unroll
        for (int rs = 0; rs < 2; ++rs) {
            y[i][rs] += __shfl_xor_sync(0xffffffffu, y[i][rs], 1);
            y[i][rs] += __shfl_xor_sync(0xffffffffu, y[i][rs], 2);
        }

    // stage partials: 4 n-warp-columns x 64 m
    float* stage = (float*)(smem + STG_B);
    if (tig == 0) {
        int col = w >> 1;
#pragma unroll
        for (int i = 0; i < 2; ++i)
#pragma unroll
            for (int rs = 0; rs < 2; ++rs) {
                int row = m0 + 16 * i + 8 * rs + gid;
                stage[col * 64 + row] = y[i][rs];
            }
    }
    __syncthreads();

    if (t < 64) {
        long row = base + t;
        float s = stage[t] + stage[64 + t] + stage[128 + t] + stage[192 + t]
                + bout[0];
        out[row] = s * (float)out_mask[row];
    }
}

// ---------------------------------------------------------------------------
extern "C" void kernel_launch(void* const* d_in, const int* in_sizes, int n_in,
                              void* d_out, int out_size) {
    const float* edges   = (const float*)d_in[0];
    const int*   in_idx  = (const int*)d_in[1];
    const int*   in_mask = (const int*)d_in[2];
    const int*   out_idx = (const int*)d_in[3];
    const int*   out_mask= (const int*)d_in[4];
    const float* W0      = (const float*)d_in[5];
    const float* b0      = (const float*)d_in[6];
    const float* W1      = (const float*)d_in[7];
    const float* b1      = (const float*)d_in[8];
    const float* Wout    = (const float*)d_in[9];
    const float* bout    = (const float*)d_in[10];
    float* out = (float*)d_out;

    int N = in_sizes[1] / K_IN;     // 200000
    int M = N * K_OUT;              // 800000 = 12500 * 64

    attn_pool_kernel<<<(N + 7) / 8, 256>>>(edges, in_idx, in_mask, N);

    cudaFuncSetAttribute(mlp_kernel,
                         cudaFuncAttributeMaxDynamicSharedMemorySize,
                         MLP_SMEM_BYTES);
    mlp_kernel<<<M / 64, 256, MLP_SMEM_BYTES>>>(
        edges, out_idx, out_mask, W0, b0, W1, b1, Wout, bout, out);
}

// round 7
// speedup vs baseline: 2.4015x; 1.2574x over previous
#include <cuda_runtime.h>
#include <cuda_bf16.h>
#include <math.h>
#include <stdint.h>

// Problem constants: N=200000, K_IN=8, K_OUT=4, E=800000, D=64, H=128, O=1
#define MAX_N 200000
#define D_DIM 64
#define K_IN 8
#define K_OUT 4
#define H_DIM 128

__device__ float g_pooled[MAX_N * D_DIM];

// ---------------------------------------------------------------------------
// helpers
// ---------------------------------------------------------------------------
__device__ __forceinline__ uint32_t smem_u32(const void* p) {
    uint32_t a;
    asm("{ .reg .u64 t; cvta.to.shared.u64 t, %1; cvt.u32.u64 %0, t; }"
        : "=r"(a) : "l"(p));
    return a;
}

// pack two floats to bf16x2: lo -> bits[15:0], hi -> bits[31:16]
__device__ __forceinline__ uint32_t bf16x2_rn(float lo, float hi) {
    uint32_t r;
    asm("cvt.rn.bf16x2.f32 %0, %1, %2;" : "=r"(r) : "f"(hi), "f"(lo));
    return r;
}

// split 8 fp32 into hi-bf16 16B chunk + lo-bf16 16B chunk
__device__ __forceinline__ void split8(const float* f, uint4& hv, uint4& lv) {
    float hf[8], lf[8];
#pragma unroll
    for (int i = 0; i < 8; ++i) {
        __nv_bfloat16 hb = __float2bfloat16(f[i]);
        hf[i] = __bfloat162float(hb);
        lf[i] = f[i] - hf[i];
    }
    hv.x = bf16x2_rn(hf[0], hf[1]); hv.y = bf16x2_rn(hf[2], hf[3]);
    hv.z = bf16x2_rn(hf[4], hf[5]); hv.w = bf16x2_rn(hf[6], hf[7]);
    lv.x = bf16x2_rn(lf[0], lf[1]); lv.y = bf16x2_rn(lf[2], lf[3]);
    lv.z = bf16x2_rn(lf[4], lf[5]); lv.w = bf16x2_rn(lf[6], lf[7]);
}

#define LDMX4(r0, r1, r2, r3, addr) \
    asm volatile("ldmatrix.sync.aligned.m8n8.x4.shared.b16 {%0,%1,%2,%3}, [%4];" \
        : "=r"(r0), "=r"(r1), "=r"(r2), "=r"(r3) : "r"(addr))

#define MMA16816(c, a, b) \
    asm volatile("mma.sync.aligned.m16n8k16.row.col.f32.bf16.bf16.f32 " \
        "{%0,%1,%2,%3}, {%4,%5,%6,%7}, {%8,%9}, {%0,%1,%2,%3};" \
        : "+f"((c)[0]), "+f"((c)[1]), "+f"((c)[2]), "+f"((c)[3]) \
        : "r"((a)[0]), "r"((a)[1]), "r"((a)[2]), "r"((a)[3]), \
          "r"((b)[0]), "r"((b)[1]))

// ---------------------------------------------------------------------------
// Kernel 1: per-node attention + pooled context (unchanged)
// ---------------------------------------------------------------------------
__global__ void __launch_bounds__(256) attn_pool_kernel(
    const float* __restrict__ edges,
    const int* __restrict__ in_idx,
    const int* __restrict__ in_mask,
    int N)
{
    __shared__ float sE[8][K_IN * 68];

    const int lane = threadIdx.x & 31;
    const int w    = threadIdx.x >> 5;
    const int node = blockIdx.x * 8 + w;
    if (node >= N) return;

    float* sEw = &sE[w][0];

    int idx_l = 0, m_l = 0;
    if (lane < K_IN) {
        idx_l = in_idx[(size_t)node * K_IN + lane];
        m_l   = in_mask[(size_t)node * K_IN + lane];
    }

    float2 r[K_IN];
#pragma unroll
    for (int k = 0; k < K_IN; ++k) {
        int ek = __shfl_sync(0xffffffffu, idx_l, k);
        float2 v = *(const float2*)(edges + (size_t)ek * D_DIM + lane * 2);
        r[k] = v;
        *(float2*)(sEw + k * 68 + lane * 2) = v;
    }
    __syncwarp();

    const int q0 = lane >> 3;
    const int kk = lane & 7;
    const float4* Eq0 = (const float4*)(sEw + q0 * 68);
    const float4* Eq1 = (const float4*)(sEw + (q0 + 4) * 68);
    const float4* Ekp = (const float4*)(sEw + kk * 68);

    float s0 = 0.f, s1 = 0.f;
#pragma unroll
    for (int d4 = 0; d4 < 16; ++d4) {
        float4 b  = Ekp[d4];
        float4 a0 = Eq0[d4];
        float4 a1 = Eq1[d4];
        s0 += a0.x * b.x + a0.y * b.y + a0.z * b.z + a0.w * b.w;
        s1 += a1.x * b.x + a1.y * b.y + a1.z * b.z + a1.w * b.w;
    }
    s0 *= 0.125f;
    s1 *= 0.125f;

    int mk = __shfl_sync(0xffffffffu, m_l, kk);
    if (!mk) { s0 = -1e9f; s1 = -1e9f; }

    float mx0 = s0, mx1 = s1;
#pragma unroll
    for (int o = 1; o < 8; o <<= 1) {
        mx0 = fmaxf(mx0, __shfl_xor_sync(0xffffffffu, mx0, o));
        mx1 = fmaxf(mx1, __shfl_xor_sync(0xffffffffu, mx1, o));
    }
    float e0 = __expf(s0 - mx0);
    float e1 = __expf(s1 - mx1);
    float z0 = e0, z1 = e1;
#pragma unroll
    for (int o = 1; o < 8; o <<= 1) {
        z0 += __shfl_xor_sync(0xffffffffu, z0, o);
        z1 += __shfl_xor_sync(0xffffffffu, z1, o);
    }
    float a0 = e0 / z0;
    float a1 = e1 / z1;

    int mq0 = __shfl_sync(0xffffffffu, m_l, q0);
    int mq1 = __shfl_sync(0xffffffffu, m_l, q0 + 4);

    float v = (mq0 ? a0 : 0.f) + (mq1 ? a1 : 0.f);
    v += __shfl_xor_sync(0xffffffffu, v, 8);
    v += __shfl_xor_sync(0xffffffffu, v, 16);

    int cnt = m_l;
#pragma unroll
    for (int o = 1; o < 32; o <<= 1)
        cnt += __shfl_xor_sync(0xffffffffu, cnt, o);
    float inv_denom = 1.f / fmaxf((float)cnt, 1.f);

    float px = 0.f, py = 0.f;
#pragma unroll
    for (int k = 0; k < K_IN; ++k) {
        float wk = __shfl_sync(0xffffffffu, v, k);
        px += wk * r[k].x;
        py += wk * r[k].y;
    }
    float2 p2 = make_float2(px * inv_denom, py * inv_denom);
    *(float2*)(g_pooled + (size_t)node * D_DIM + lane * 2) = p2;
}

// ---------------------------------------------------------------------------
// Kernel 2: fused 3-layer MLP with HMMA, hi/lo split, FUSED 3-pass k-loop.
// CTA: 256 threads (8 warps), 64 rows. 2 CTAs/SM.
// SMEM byte layout (per CTA):
//   XHI@0      [64 m][128 k] bf16  (16 KB)    rows 256B, 16B-chunk XOR swizzle
//   XLO@16384  (16 KB)
//   WHI@32768  [128 h][128 k] bf16 (32 KB)
//   WLO@65536  (32 KB)
//   STG@98304  4 x 64 fp32 partials (1 KB)
// Warp grid: m0 = (w&1)*32, n0 = (w>>1)*32; warp tile 32m x 32n.
// Per k-chunk: load Ahi,Alo,Bhi,Blo once (8 ldmatrix.x4), run 24 MMAs:
//   acc += Ahi*Bhi + Ahi*Blo + Alo*Bhi
// ---------------------------------------------------------------------------
#define XHI_B 0u
#define XLO_B 16384u
#define WHI_B 32768u
#define WLO_B 65536u
#define STG_B 98304u
#define MLP_SMEM_BYTES 99328

// byte offset inside a buffer for (row, 16B-chunk)
__device__ __forceinline__ uint32_t swz(int row, int chunk) {
    return (uint32_t)row * 256u + (uint32_t)((chunk ^ (row & 7)) << 4);
}

// fused 3-pass GEMM over k=128
__device__ __forceinline__ void gemm_fused(
    uint32_t XH, uint32_t XL, uint32_t WH, uint32_t WL,
    uint32_t aOff0, uint32_t aOff1, uint32_t aKey, uint32_t cbA,
    uint32_t bOff0, uint32_t bOff1, uint32_t bKey, uint32_t cbB,
    float acc[2][4][4])
{
#pragma unroll
    for (int kc = 0; kc < 8; ++kc) {
        uint32_t ca = (uint32_t)((((2 * kc + cbA)) ^ aKey) << 4);
        uint32_t cb = (uint32_t)((((2 * kc + cbB)) ^ bKey) << 4);
        uint32_t ah0[4], ah1[4], al0[4], al1[4];
        uint32_t bh0[4], bh1[4], bl0[4], bl1[4];
        LDMX4(ah0[0], ah0[1], ah0[2], ah0[3], XH + aOff0 + ca);
        LDMX4(ah1[0], ah1[1], ah1[2], ah1[3], XH + aOff1 + ca);
        LDMX4(bh0[0], bh0[1], bh0[2], bh0[3], WH + bOff0 + cb);
        LDMX4(bh1[0], bh1[1], bh1[2], bh1[3], WH + bOff1 + cb);
        LDMX4(al0[0], al0[1], al0[2], al0[3], XL + aOff0 + ca);
        LDMX4(al1[0], al1[1], al1[2], al1[3], XL + aOff1 + ca);
        LDMX4(bl0[0], bl0[1], bl0[2], bl0[3], WL + bOff0 + cb);
        LDMX4(bl1[0], bl1[1], bl1[2], bl1[3], WL + bOff1 + cb);
        // Ahi * Bhi
        MMA16816(acc[0][0], ah0, bh0 + 0);
        MMA16816(acc[0][1], ah0, bh0 + 2);
        MMA16816(acc[0][2], ah0, bh1 + 0);
        MMA16816(acc[0][3], ah0, bh1 + 2);
        MMA16816(acc[1][0], ah1, bh0 + 0);
        MMA16816(acc[1][1], ah1, bh0 + 2);
        MMA16816(acc[1][2], ah1, bh1 + 0);
        MMA16816(acc[1][3], ah1, bh1 + 2);
        // Ahi * Blo
        MMA16816(acc[0][0], ah0, bl0 + 0);
        MMA16816(acc[0][1], ah0, bl0 + 2);
        MMA16816(acc[0][2], ah0, bl1 + 0);
        MMA16816(acc[0][3], ah0, bl1 + 2);
        MMA16816(acc[1][0], ah1, bl0 + 0);
        MMA16816(acc[1][1], ah1, bl0 + 2);
        MMA16816(acc[1][2], ah1, bl1 + 0);
        MMA16816(acc[1][3], ah1, bl1 + 2);
        // Alo * Bhi
        MMA16816(acc[0][0], al0, bh0 + 0);
        MMA16816(acc[0][1], al0, bh0 + 2);
        MMA16816(acc[0][2], al0, bh1 + 0);
        MMA16816(acc[0][3], al0, bh1 + 2);
        MMA16816(acc[1][0], al1, bh0 + 0);
        MMA16816(acc[1][1], al1, bh0 + 2);
        MMA16816(acc[1][2], al1, bh1 + 0);
        MMA16816(acc[1][3], al1, bh1 + 2);
    }
}

// load weight matrix W [128][128] fp32 -> hi/lo bf16 buffers (swizzled)
__device__ __forceinline__ void load_w_split(
    char* smem, uint32_t hi_off, uint32_t lo_off,
    const float* __restrict__ W, int t)
{
    const int h    = t & 127;
    const int half = t >> 7;
    const int key  = h & 7;
    const float4* src = (const float4*)(W + (size_t)h * H_DIM + half * 64);
#pragma unroll
    for (int c = 0; c < 8; ++c) {
        float4 f0 = src[2 * c], f1 = src[2 * c + 1];
        float f[8] = {f0.x, f0.y, f0.z, f0.w, f1.x, f1.y, f1.z, f1.w};
        uint4 hv, lv;
        split8(f, hv, lv);
        int chunk = half * 8 + c;
        uint32_t off = (uint32_t)h * 256u + (uint32_t)((chunk ^ key) << 4);
        *(uint4*)(smem + hi_off + off) = hv;
        *(uint4*)(smem + lo_off + off) = lv;
    }
}

__global__ void __launch_bounds__(256, 2) mlp_kernel(
    const float* __restrict__ edges,
    const int* __restrict__ out_idx,
    const int* __restrict__ out_mask,
    const float* __restrict__ W0,
    const float* __restrict__ b0,
    const float* __restrict__ W1,
    const float* __restrict__ b1,
    const float* __restrict__ Wout,
    const float* __restrict__ bout,
    float* __restrict__ out)
{
    extern __shared__ char smem[];
    const uint32_t sb = smem_u32(smem);

    const int t    = threadIdx.x;
    const int lane = t & 31;
    const int w    = t >> 5;
    const int gid  = lane >> 2;     // 0..7
    const int tig  = lane & 3;      // 0..3
    const int m0   = (w & 1) * 32;
    const int n0   = (w >> 1) * 32;
    const long base = (long)blockIdx.x * 64;    // M = 800000 = 12500*64

    // ---- load X = [edges | pooled] -> hi/lo bf16 swizzled ----
    {
        const int row = t & 63;
        const int kq  = t >> 6;     // 0..3 (32 k each)
        long grow = base + row;
        const float* src;
        if (kq < 2) {
            int eidx = out_idx[grow];
            src = edges + (size_t)eidx * D_DIM + kq * 32;
        } else {
            src = g_pooled + (size_t)(grow >> 2) * D_DIM + (kq - 2) * 32;
        }
        const float4* s4 = (const float4*)src;
        const int cbase = kq * 4;
#pragma unroll
        for (int c = 0; c < 4; ++c) {
            float4 f0 = s4[2 * c], f1 = s4[2 * c + 1];
            float f[8] = {f0.x, f0.y, f0.z, f0.w, f1.x, f1.y, f1.z, f1.w};
            uint4 hv, lv;
            split8(f, hv, lv);
            uint32_t off = swz(row, cbase + c);
            *(uint4*)(smem + XHI_B + off) = hv;
            *(uint4*)(smem + XLO_B + off) = lv;
        }
    }
    load_w_split(smem, WHI_B, WLO_B, W0, t);
    __syncthreads();

    // ---- per-lane ldmatrix geometry ----
    const int sub = lane >> 3;      // 0..3 (matrix slot)
    const int r8  = lane & 7;
    const int aRow = m0 + (sub & 1) * 8 + r8;       // i=0 tile; i=1 adds 16
    const uint32_t aOff0 = (uint32_t)aRow * 256u;
    const uint32_t aOff1 = (uint32_t)(aRow + 16) * 256u;
    const uint32_t aKey  = (uint32_t)(aRow & 7);
    const uint32_t cbA   = (uint32_t)(sub >> 1);
    const int bRow = n0 + (sub >> 1) * 8 + r8;      // j=0 tile; j=1 adds 16
    const uint32_t bOff0 = (uint32_t)bRow * 256u;
    const uint32_t bOff1 = (uint32_t)(bRow + 16) * 256u;
    const uint32_t bKey  = (uint32_t)(bRow & 7);
    const uint32_t cbB   = (uint32_t)(sub & 1);

    const uint32_t XH = sb + XHI_B, XL = sb + XLO_B;
    const uint32_t WH = sb + WHI_B, WL = sb + WLO_B;

    // ---- GEMM layer 1 ----
    float acc[2][4][4];
#pragma unroll
    for (int i = 0; i < 2; ++i)
#pragma unroll
        for (int j = 0; j < 4; ++j)
#pragma unroll
            for (int p = 0; p < 4; ++p) acc[i][j][p] = 0.f;

    gemm_fused(XH, XL, WH, WL, aOff0, aOff1, aKey, cbA,
               bOff0, bOff1, bKey, cbB, acc);

    __syncthreads();   // all reads of X/W done

    // ---- epilogue 1: H = relu(acc + b0) -> X buffers (bf16 hi/lo) ----
#pragma unroll
    for (int j = 0; j < 4; ++j) {
        int h0 = n0 + 8 * j + 2 * tig;
        float2 bb = *(const float2*)(b0 + h0);
        int chunk = (n0 + 8 * j) >> 3;
        uint32_t cof = (uint32_t)(tig * 4);
#pragma unroll
        for (int i = 0; i < 2; ++i) {
#pragma unroll
            for (int rs = 0; rs < 2; ++rs) {
                int row = m0 + 16 * i + 8 * rs + gid;
                float v0 = fmaxf(acc[i][j][2 * rs]     + bb.x, 0.f);
                float v1 = fmaxf(acc[i][j][2 * rs + 1] + bb.y, 0.f);
                __nv_bfloat16 h0b = __float2bfloat16(v0);
                __nv_bfloat16 h1b = __float2bfloat16(v1);
                float l0 = v0 - __bfloat162float(h0b);
                float l1 = v1 - __bfloat162float(h1b);
                uint32_t hw = bf16x2_rn(__bfloat162float(h0b), __bfloat162float(h1b));
                uint32_t lw = bf16x2_rn(l0, l1);
                uint32_t off = (uint32_t)row * 256u
                             + (uint32_t)((chunk ^ (row & 7)) << 4) + cof;
                *(uint32_t*)(smem + XHI_B + off) = hw;
                *(uint32_t*)(smem + XLO_B + off) = lw;
            }
        }
    }
    load_w_split(smem, WHI_B, WLO_B, W1, t);
    __syncthreads();

    // ---- GEMM layer 2 ----
#pragma unroll
    for (int i = 0; i < 2; ++i)
#pragma unroll
        for (int j = 0; j < 4; ++j)
#pragma unroll
            for (int p = 0; p < 4; ++p) acc[i][j][p] = 0.f;

    gemm_fused(XH, XL, WH, WL, aOff0, aOff1, aKey, cbA,
               bOff0, bOff1, bKey, cbB, acc);

    // ---- final epilogue: relu(+b1), dot Wout, reduce ----
    float y[2][2] = {{0.f, 0.f}, {0.f, 0.f}};   // [i][rowsub]
#pragma unroll
    for (int j = 0; j < 4; ++j) {
        int h0 = n0 + 8 * j + 2 * tig;
        float2 bb = *(const float2*)(b1 + h0);
        float2 ww = *(const float2*)(Wout + h0);
#pragma unroll
        for (int i = 0; i < 2; ++i) {
#pragma unroll
            for (int rs = 0; rs < 2; ++rs) {
                float v0 = fmaxf(acc[i][j][2 * rs]     + bb.x, 0.f);
                float v1 = fmaxf(acc[i][j][2 * rs + 1] + bb.y, 0.f);
                y[i][rs] += ww.x * v0 + ww.y * v1;
            }
        }
    }
    // reduce over tig lanes (bits 0,1)
#pragma unroll
    for (int i = 0; i < 2; ++i)
#pragma unroll
        for (int rs = 0; rs < 2; ++rs) {
            y[i][rs] += __shfl_xor_sync(0xffffffffu, y[i][rs], 1);
            y[i][rs] += __shfl_xor_sync(0xffffffffu, y[i][rs], 2);
        }

    // stage partials: 4 n-warp-columns x 64 m
    float* stage = (float*)(smem + STG_B);
    if (tig == 0) {
        int col = w >> 1;
#pragma unroll
        for (int i = 0; i < 2; ++i)
#pragma unroll
            for (int rs = 0; rs < 2; ++rs) {
                int row = m0 + 16 * i + 8 * rs + gid;
                stage[col * 64 + row] = y[i][rs];
            }
    }
    __syncthreads();

    if (t < 64) {
        long row = base + t;
        float s = stage[t] + stage[64 + t] + stage[128 + t] + stage[192 + t]
                + bout[0];
        out[row] = s * (float)out_mask[row];
    }
}

// ---------------------------------------------------------------------------
extern "C" void kernel_launch(void* const* d_in, const int* in_sizes, int n_in,
                              void* d_out, int out_size) {
    const float* edges   = (const float*)d_in[0];
    const int*   in_idx  = (const int*)d_in[1];
    const int*   in_mask = (const int*)d_in[2];
    const int*   out_idx = (const int*)d_in[3];
    const int*   out_mask= (const int*)d_in[4];
    const float* W0      = (const float*)d_in[5];
    const float* b0      = (const float*)d_in[6];
    const float* W1      = (const float*)d_in[7];
    const float* b1      = (const float*)d_in[8];
    const float* Wout    = (const float*)d_in[9];
    const float* bout    = (const float*)d_in[10];
    float* out = (float*)d_out;

    int N = in_sizes[1] / K_IN;     // 200000
    int M = N * K_OUT;              // 800000 = 12500 * 64

    attn_pool_kernel<<<(N + 7) / 8, 256>>>(edges, in_idx, in_mask, N);

    cudaFuncSetAttribute(mlp_kernel,
                         cudaFuncAttributeMaxDynamicSharedMemorySize,
                         MLP_SMEM_BYTES);
    mlp_kernel<<<M / 64, 256, MLP_SMEM_BYTES>>>(
        edges, out_idx, out_mask, W0, b0, W1, b1, Wout, bout, out);
}